// round 7
// baseline (speedup 1.0000x reference)
#include <cuda_runtime.h>
#include <cuda_bf16.h>
#include <math.h>

// Problem constants: B=2, L=128, H=768, C=6, nhops=2
#define NC  6
#define LL  128
#define KP  1600     // padded K (1554 -> 1600)
#define MP  640      // padded M (513 -> 640)
#define NF  1536     // output feature width

typedef unsigned int u32;
typedef unsigned short u16;

// Scratch (allocation-free: __device__ globals)
__device__ __align__(16) __nv_bfloat16 g_A[2][2][MP * KP];   // [set][hi/lo], row-major [MP][KP]
__device__ __align__(16) __nv_bfloat16 g_Wt[2][NF * KP];     // [hi/lo], W^T: row n, col k
__device__ __align__(16) float g_clsT[NC * 1536];
__device__ float g_pqr2[2][513 * NC];       // ping-pong: 0..255 p, 256..511 q, 512 r
__device__ float g_pp[48 * MP * NC];        // per-(nCTA,wn) probs partials

__device__ __forceinline__ void bsplit(float v, u16& h, u16& l) {
    __nv_bfloat16 hb = __float2bfloat16(v);
    __nv_bfloat16 lb = __float2bfloat16(v - __bfloat162float(hb));
    h = *(u16*)&hb; l = *(u16*)&lb;
}
__device__ __forceinline__ u32 smem_u32(const void* p) {
    u32 a;
    asm("{ .reg .u64 t; cvta.to.shared.u64 t, %1; cvt.u32.u64 %0, t; }" : "=r"(a) : "l"(p));
    return a;
}
__device__ __forceinline__ void cpa16(u32 s, const void* g) {
    asm volatile("cp.async.cg.shared.global [%0], [%1], 16;" :: "r"(s), "l"(g));
}
__device__ __forceinline__ u32 lds32(u32 a) {
    u32 x; asm volatile("ld.shared.b32 %0, [%1];" : "=r"(x) : "r"(a)); return x;
}
__device__ __forceinline__ void mma16816(float* c, const u32* a, u32 b0, u32 b1) {
    asm volatile("mma.sync.aligned.m16n8k16.row.col.f32.bf16.bf16.f32 "
        "{%0,%1,%2,%3},{%4,%5,%6,%7},{%8,%9},{%0,%1,%2,%3};"
        : "+f"(c[0]), "+f"(c[1]), "+f"(c[2]), "+f"(c[3])
        : "r"(a[0]), "r"(a[1]), "r"(a[2]), "r"(a[3]), "r"(b0), "r"(b1));
}

// ================= fused one-time prep =================
// blocks [0,2400): transpose+split feat_w -> g_Wt  (+ clsT build piggybacked)
// blocks [2400,3040): init A set0 bf16 hi/lo, zero pads + ext cols
// blocks [3040,3296): probs0 from hidden (self-staged cls_w transpose in smem)
#define PREP_CONVW 2400
#define PREP_INIT  640
__global__ void __launch_bounds__(256) k_prep(const float* __restrict__ feat_w,
                                              const float* __restrict__ cls_w,
                                              const float* __restrict__ hidden,
                                              const float* __restrict__ cls_b) {
    __shared__ float sbuf[NC * 1536];                // 36 KB; convW uses first 32*33
    int blk = blockIdx.x, tid = threadIdx.x;

    if (blk < PREP_CONVW) {
        // ---- convW: k tile bk (0..49), n tile bn (0..47) ----
        int bk = blk % 50, bn = blk / 50;
        int tx = tid & 31, ty = tid >> 5;            // 32 x 8
        #pragma unroll
        for (int i = 0; i < 32; i += 8) {
            int k = bk * 32 + ty + i;
            sbuf[(ty + i) * 33 + tx] = (k < 1554) ? feat_w[(size_t)k * 1536 + bn * 32 + tx] : 0.f;
        }
        __syncthreads();
        #pragma unroll
        for (int i = 0; i < 32; i += 8) {
            int n = bn * 32 + ty + i;
            int k = bk * 32 + tx;
            u16 h, l; bsplit(sbuf[tx * 33 + ty + i], h, l);
            *(u16*)&g_Wt[0][(size_t)n * KP + k] = h;
            *(u16*)&g_Wt[1][(size_t)n * KP + k] = l;
        }
        // piggyback clsT build on first 36 blocks (one 256-chunk each)
        if (blk < 36) {
            int t = blk * 256 + tid;
            if (t < NC * 1536) {
                int c = t / 1536, k = t % 1536;
                g_clsT[t] = cls_w[k * NC + c];
            }
        }
    } else if (blk < PREP_CONVW + PREP_INIT) {
        // ---- init: row of A set0; zero pad rows + ext cols of set1 ----
        int row = blk - PREP_CONVW;                  // 0..639
        for (int c = tid; c < KP; c += 256) {
            float v = 0.f;
            if (row < 256)      { if (c < 768) v = hidden[row * 768 + c]; }
            else if (row < 512) { if (c >= 768 && c < 1536) v = hidden[(row - 256) * 768 + c - 768]; }
            u16 h, l; bsplit(v, h, l);
            *(u16*)&g_A[0][0][(size_t)row * KP + c] = h;
            *(u16*)&g_A[0][1][(size_t)row * KP + c] = l;
            if (row >= 513) {                        // pad rows of set1: zero everything
                *(u16*)&g_A[1][0][(size_t)row * KP + c] = 0;
                *(u16*)&g_A[1][1][(size_t)row * KP + c] = 0;
            } else if (c >= 1536) {                  // ext cols of set1 valid rows: zero once
                *(u16*)&g_A[1][0][(size_t)row * KP + c] = 0;
                *(u16*)&g_A[1][1][(size_t)row * KP + c] = 0;
            }
        }
    } else {
        // ---- probs0: row (0..255), 6 channel-warps, cls_w staged in smem ----
        int row = blk - (PREP_CONVW + PREP_INIT);
        for (int idx = tid; idx < NC * 1536; idx += 256) {
            // cls_w linear [k][c]; transpose into sbuf[c][k]
            sbuf[(idx % NC) * 1536 + idx / NC] = cls_w[idx];
        }
        __syncthreads();
        int warp = tid >> 5, lane = tid & 31;        // 8 warps, 6 active
        if (warp < NC) {
            const float4* hr = (const float4*)(hidden + (size_t)row * 768);
            const float4* w0 = (const float4*)(sbuf + warp * 1536);
            const float4* w1 = (const float4*)(sbuf + warp * 1536 + 768);
            float sp = 0.f, sq = 0.f;
            #pragma unroll
            for (int it = 0; it < 6; it++) {         // 6*32*4 = 768
                int k4 = it * 32 + lane;
                float4 a = hr[k4], b = w0[k4], c = w1[k4];
                sp += a.x * b.x + a.y * b.y + a.z * b.z + a.w * b.w;
                sq += a.x * c.x + a.y * c.y + a.z * c.z + a.w * c.w;
            }
            #pragma unroll
            for (int o = 16; o; o >>= 1) {
                sp += __shfl_down_sync(0xffffffffu, sp, o);
                sq += __shfl_down_sync(0xffffffffu, sq, o);
            }
            if (lane == 0) {
                g_pqr2[0][row * NC + warp] = sp;
                g_pqr2[0][(256 + row) * NC + warp] = sq;
                if (row == 0) g_pqr2[0][512 * NC + warp] = cls_b[warp];
            }
        }
    }
}

// ================= fused masked max-pool + ext-column write =================
// 12 blocks (b,c) x 128 threads; writes bf16 hi/lo ext cols 1536..1553 of A[set]
__global__ void k_poolext(const float* __restrict__ am, int src, int set) {
    int b = blockIdx.x / NC, c = blockIdx.x % NC;
    __shared__ float sp[LL], sq[LL], sm[LL];
    const float* pqr = g_pqr2[src];
    __nv_bfloat16* Ah = g_A[set][0];
    __nv_bfloat16* Al = g_A[set][1];
    int k = threadIdx.x;                             // 128 threads
    sp[k] = pqr[(b * LL + k) * NC + c];
    sq[k] = pqr[(256 + b * LL + k) * NC + c];
    sm[k] = am[b * LL + k];
    __syncthreads();
    float r  = pqr[512 * NC + c];
    float mk = sm[k], pk = sp[k], qk = sq[k];
    float mx = -INFINITY;
    #pragma unroll 4
    for (int i = 0; i < LL; i++) {
        float mi  = sm[i];
        float mv1 = (i <= k) ? mi * mk : 0.f;        // column k over i
        mx = fmaxf(mx, (sp[i] + qk + r) * mv1);
        float mv2 = (i >= k) ? mk * mi : 0.f;        // row k over j
        mx = fmaxf(mx, (pk + sq[i] + r) * mv2);
    }
    int rowP = b * LL + k, rowQ = 256 + b * LL + k;
    u16 h, l;
    bsplit(mx, h, l);                                // pooled: P rows col 1536+c, Q rows col 1542+c
    *(u16*)&Ah[(size_t)rowP * KP + 1536 + c] = h; *(u16*)&Al[(size_t)rowP * KP + 1536 + c] = l;
    *(u16*)&Ah[(size_t)rowQ * KP + 1542 + c] = h; *(u16*)&Al[(size_t)rowQ * KP + 1542 + c] = l;
    bsplit(pk, h, l);                                // probs: P rows col 1548+c
    *(u16*)&Ah[(size_t)rowP * KP + 1548 + c] = h; *(u16*)&Al[(size_t)rowP * KP + 1548 + c] = l;
    bsplit(qk, h, l);                                // probs: Q rows col 1548+c
    *(u16*)&Ah[(size_t)rowQ * KP + 1548 + c] = h; *(u16*)&Al[(size_t)rowQ * KP + 1548 + c] = l;
    if (b == 0 && k == 0) {                          // R row
        bsplit(r, h, l);
        *(u16*)&Ah[(size_t)512 * KP + 1548 + c] = h; *(u16*)&Al[(size_t)512 * KP + 1548 + c] = l;
    }
}

// ================= HMMA split-bf16 GEMM, fused probs epilogue =================
// CTA 128x64, 8 warps (4m x 2n, warp tile 32x32), 3-stage cp.async pipeline.
#define STG 30720     // Ah 10240 | Al 10240 | Bh 5120 | Bl 5120   (pitch 80B)
__global__ void __launch_bounds__(256, 1) k_gemm(int set, const float* __restrict__ bias) {
    extern __shared__ __align__(16) char smem[];
    const __nv_bfloat16* Ah = g_A[set][0];
    const __nv_bfloat16* Al = g_A[set][1];
    __nv_bfloat16* Aoh = g_A[set ^ 1][0];
    __nv_bfloat16* Aol = g_A[set ^ 1][1];

    const int tid = threadIdx.x;
    const int m0 = blockIdx.y * 128, n0 = blockIdx.x * 64;
    const u32 sb = smem_u32(smem);

    const int r4 = tid >> 2, q4 = (tid & 3) * 16;    // copy row/chunk
    const char* gAh = (const char*)Ah + (size_t)(m0 + r4) * (KP * 2) + q4;
    const char* gAl = (const char*)Al + (size_t)(m0 + r4) * (KP * 2) + q4;
    const char* gBh = (const char*)g_Wt[0] + (size_t)(n0 + r4) * (KP * 2) + q4;
    const char* gBl = (const char*)g_Wt[1] + (size_t)(n0 + r4) * (KP * 2) + q4;

    #define COPY_STAGE(s, kt) do {                                            \
        u32 d = sb + (s) * STG;                                               \
        int kb = (kt) * 64;                                                   \
        cpa16(d +         r4 * 80 + q4,        gAh + kb);                     \
        cpa16(d +         (64 + r4) * 80 + q4, gAh + kb + 64 * KP * 2);       \
        cpa16(d + 10240 + r4 * 80 + q4,        gAl + kb);                     \
        cpa16(d + 10240 + (64 + r4) * 80 + q4, gAl + kb + 64 * KP * 2);       \
        cpa16(d + 20480 + r4 * 80 + q4,        gBh + kb);                     \
        cpa16(d + 25600 + r4 * 80 + q4,        gBl + kb);                     \
        asm volatile("cp.async.commit_group;" ::: "memory");                  \
    } while (0)

    COPY_STAGE(0, 0);
    COPY_STAGE(1, 1);

    const int wid = tid >> 5, lane = tid & 31;
    const int wm = wid & 3, wn = wid >> 2;           // warp grid 4(m) x 2(n)
    const int g = lane >> 2, t = lane & 3;
    const u32 a_off = (u32)((wm * 32 + g) * 80 + t * 4);
    const u32 b_off = (u32)(20480 + (wn * 32 + g) * 80 + t * 4);

    float acc[2][4][4];
    #pragma unroll
    for (int mt = 0; mt < 2; mt++)
        #pragma unroll
        for (int nt = 0; nt < 4; nt++)
            #pragma unroll
            for (int i = 0; i < 4; i++) acc[mt][nt][i] = 0.f;

    for (int kt = 0; kt < 50; kt++) {
        if (kt < 49) asm volatile("cp.async.wait_group 1;" ::: "memory");
        else         asm volatile("cp.async.wait_group 0;" ::: "memory");
        __syncthreads();
        u32 st = sb + (kt % 3) * STG;
        #pragma unroll
        for (int kk = 0; kk < 2; kk++) {             // two k16 halves (32B each)
            u32 ka = st + a_off + kk * 32;
            u32 kb = st + b_off + kk * 32;
            u32 ah[2][4], al[2][4];
            #pragma unroll
            for (int mt = 0; mt < 2; mt++) {
                u32 base = ka + mt * 1280;           // 16 rows * 80B
                ah[mt][0] = lds32(base);
                ah[mt][1] = lds32(base + 640);       // +8 rows
                ah[mt][2] = lds32(base + 16);        // +8 k
                ah[mt][3] = lds32(base + 656);
                al[mt][0] = lds32(base + 10240);
                al[mt][1] = lds32(base + 10880);
                al[mt][2] = lds32(base + 10256);
                al[mt][3] = lds32(base + 10896);
            }
            #pragma unroll
            for (int nt = 0; nt < 4; nt++) {
                u32 bb  = kb + nt * 640;             // +8 n rows
                u32 bh0 = lds32(bb),        bh1 = lds32(bb + 16);
                u32 bl0 = lds32(bb + 5120), bl1 = lds32(bb + 5136);
                #pragma unroll
                for (int mt = 0; mt < 2; mt++) {
                    mma16816(acc[mt][nt], ah[mt], bh0, bh1);
                    mma16816(acc[mt][nt], ah[mt], bl0, bl1);
                    mma16816(acc[mt][nt], al[mt], bh0, bh1);
                }
            }
        }
        if (kt + 2 < 50) COPY_STAGE((kt + 2) % 3, kt + 2);
    }

    // ---- epilogue ----
    #pragma unroll
    for (int mt = 0; mt < 2; mt++)
        #pragma unroll
        for (int half = 0; half < 2; half++) {
            int r = m0 + wm * 32 + mt * 16 + g + half * 8;
            if (r == 512) {
                #pragma unroll
                for (int nt = 0; nt < 4; nt++) {
                    int col = n0 + wn * 32 + nt * 8 + t * 2;
                    acc[mt][nt][half * 2]     += bias[col];
                    acc[mt][nt][half * 2 + 1] += bias[col + 1];
                }
            }
        }

    // next-hop bf16 hi/lo A
    #pragma unroll
    for (int mt = 0; mt < 2; mt++)
        #pragma unroll
        for (int nt = 0; nt < 4; nt++) {
            int col = n0 + wn * 32 + nt * 8 + t * 2;
            #pragma unroll
            for (int half = 0; half < 2; half++) {
                int r = m0 + wm * 32 + mt * 16 + g + half * 8;
                if (r < 513) {
                    u16 h0, l0, h1, l1;
                    bsplit(acc[mt][nt][half * 2], h0, l0);
                    bsplit(acc[mt][nt][half * 2 + 1], h1, l1);
                    *(u32*)(Aoh + (size_t)r * KP + col) = (u32)h0 | ((u32)h1 << 16);
                    *(u32*)(Aol + (size_t)r * KP + col) = (u32)l0 | ((u32)l1 << 16);
                }
            }
        }

    // probs partials: part[r][c] = sum over this warp's 32 cols of C[r,col]*clsT[c][col]
    float* pp = g_pp + (size_t)(blockIdx.x * 2 + wn) * (MP * NC);
    #pragma unroll
    for (int c = 0; c < NC; c++) {
        float cv[4][2];
        #pragma unroll
        for (int nt = 0; nt < 4; nt++) {
            int col = n0 + wn * 32 + nt * 8 + t * 2;
            cv[nt][0] = g_clsT[c * 1536 + col];
            cv[nt][1] = g_clsT[c * 1536 + col + 1];
        }
        #pragma unroll
        for (int mt = 0; mt < 2; mt++)
            #pragma unroll
            for (int half = 0; half < 2; half++) {
                float s = 0.f;
                #pragma unroll
                for (int nt = 0; nt < 4; nt++)
                    s += acc[mt][nt][half * 2] * cv[nt][0]
                       + acc[mt][nt][half * 2 + 1] * cv[nt][1];
                s += __shfl_xor_sync(0xffffffffu, s, 1);
                s += __shfl_xor_sync(0xffffffffu, s, 2);
                if (t == 0) {
                    int r = m0 + wm * 32 + mt * 16 + g + half * 8;
                    if (r < 513) pp[r * NC + c] = s;
                }
            }
    }
    #undef COPY_STAGE
}

// ================= reduce probs partials =================
__global__ void k_red(int dst, const float* __restrict__ cls_b) {
    int gw = blockIdx.x * 8 + (threadIdx.x >> 5);    // 0..3077
    int lane = threadIdx.x & 31;
    if (gw >= 513 * NC) return;
    int row = gw / NC, c = gw % NC;
    float s = g_pp[(size_t)lane * (MP * NC) + row * NC + c]
            + g_pp[(size_t)(lane + 32) * (MP * NC) + ((lane + 32) < 48 ? row * NC + c : 0)] * ((lane + 32) < 48 ? 1.f : 0.f);
    #pragma unroll
    for (int o = 16; o; o >>= 1) s += __shfl_down_sync(0xffffffffu, s, o);
    if (lane == 0) {
        if (row == 512) s += cls_b[c];
        g_pqr2[dst][row * NC + c] = s;
    }
}

// ================= final: logits[b,i,j,c] = p + q + r =================
__global__ void k_out(float* __restrict__ out) {
    int idx = blockIdx.x * 256 + threadIdx.x;        // 0..196607 exact
    int c = idx % NC;
    int j = (idx / NC) % LL;
    int t = idx / (NC * LL);
    int i = t % LL;
    int b = t / LL;
    const float* pqr = g_pqr2[0];
    out[idx] = pqr[(b * LL + i) * NC + c]
             + pqr[(256 + b * LL + j) * NC + c]
             + pqr[512 * NC + c];
}

extern "C" void kernel_launch(void* const* d_in, const int* in_sizes, int n_in,
                              void* d_out, int out_size) {
    const float* hidden = (const float*)d_in[0];
    const float* am     = (const float*)d_in[1];
    const float* cls_w  = (const float*)d_in[2];
    const float* cls_b  = (const float*)d_in[3];
    const float* feat_w = (const float*)d_in[4];
    const float* feat_b = (const float*)d_in[5];

    cudaFuncSetAttribute(k_gemm, cudaFuncAttributeMaxDynamicSharedMemorySize, 3 * STG);

    k_prep<<<3296, 256>>>(feat_w, cls_w, hidden, cls_b);

    for (int h = 0; h < 2; h++) {
        k_poolext<<<12, 128>>>(am, h, h);            // src = set = h
        k_gemm<<<dim3(24, 5), 256, 3 * STG>>>(h, feat_b);
        k_red<<<385, 256>>>(h ^ 1, cls_b);
    }
    k_out<<<768, 256>>>((float*)d_out);
}

// round 8
// speedup vs baseline: 1.3340x; 1.3340x over previous
#include <cuda_runtime.h>
#include <cuda_bf16.h>
#include <math.h>

// Problem constants: B=2, L=128, H=768, C=6, nhops=2
#define NC  6
#define LL  128
#define KP  1600     // padded K (1554 -> 1600)
#define MP  640      // padded M (513 -> 640)
#define NF  1536     // output feature width

typedef unsigned int u32;
typedef unsigned short u16;

// Scratch (allocation-free: __device__ globals)
__device__ __align__(16) __nv_bfloat16 g_A[2][2][MP * KP];   // [set][hi/lo], row-major [MP][KP]
__device__ __align__(16) __nv_bfloat16 g_Wt[2][NF * KP];     // [hi/lo], W^T: row n, col k
__device__ __align__(16) float g_clsT[NC * 1536];
__device__ float g_pqr2[2][513 * NC];       // 0..255 p, 256..511 q, 512 r
__device__ __align__(16) float g_pp[513 * NC * 48];  // probs partials [row*NC+c][slab]

__device__ __forceinline__ void bsplit(float v, u16& h, u16& l) {
    __nv_bfloat16 hb = __float2bfloat16(v);
    __nv_bfloat16 lb = __float2bfloat16(v - __bfloat162float(hb));
    h = *(u16*)&hb; l = *(u16*)&lb;
}
__device__ __forceinline__ u32 smem_u32(const void* p) {
    u32 a;
    asm("{ .reg .u64 t; cvta.to.shared.u64 t, %1; cvt.u32.u64 %0, t; }" : "=r"(a) : "l"(p));
    return a;
}
__device__ __forceinline__ void cpa16(u32 s, const void* g) {
    asm volatile("cp.async.cg.shared.global [%0], [%1], 16;" :: "r"(s), "l"(g));
}
__device__ __forceinline__ u32 lds32(u32 a) {
    u32 x; asm volatile("ld.shared.b32 %0, [%1];" : "=r"(x) : "r"(a)); return x;
}
__device__ __forceinline__ void mma16816(float* c, const u32* a, u32 b0, u32 b1) {
    asm volatile("mma.sync.aligned.m16n8k16.row.col.f32.bf16.bf16.f32 "
        "{%0,%1,%2,%3},{%4,%5,%6,%7},{%8,%9},{%0,%1,%2,%3};"
        : "+f"(c[0]), "+f"(c[1]), "+f"(c[2]), "+f"(c[3])
        : "r"(a[0]), "r"(a[1]), "r"(a[2]), "r"(a[3]), "r"(b0), "r"(b1));
}

// ================= (1) transpose+split feat_w -> g_Wt; clsT piggyback =================
__global__ void k_convW(const float* __restrict__ feat_w, const float* __restrict__ cls_w) {
    __shared__ float ts[32][33];
    int blk = blockIdx.x;                            // 0..2399
    int bk = blk % 50, bn = blk / 50;                // k tile, n tile
    int tx = threadIdx.x & 31, ty = threadIdx.x >> 5;
    #pragma unroll
    for (int i = 0; i < 32; i += 8) {
        int k = bk * 32 + ty + i;
        ts[ty + i][tx] = (k < 1554) ? feat_w[(size_t)k * 1536 + bn * 32 + tx] : 0.f;
    }
    __syncthreads();
    #pragma unroll
    for (int i = 0; i < 32; i += 8) {
        int n = bn * 32 + ty + i;
        int k = bk * 32 + tx;
        u16 h, l; bsplit(ts[tx][ty + i], h, l);
        *(u16*)&g_Wt[0][(size_t)n * KP + k] = h;
        *(u16*)&g_Wt[1][(size_t)n * KP + k] = l;
    }
    if (blk < 36) {                                  // clsT piggyback
        int t = blk * 256 + threadIdx.x;
        if (t < NC * 1536) {
            int c = t / 1536, k = t % 1536;
            g_clsT[t] = cls_w[k * NC + c];
        }
    }
}

// ================= (2) init: A set0 bf16 hi/lo; zero pads + set1 ext tail =================
__global__ void k_init(const float* __restrict__ hidden) {
    int row = blockIdx.x;                            // 0..639
    for (int c = threadIdx.x; c < KP; c += 256) {
        float v = 0.f;
        if (row < 256)      { if (c < 768) v = hidden[row * 768 + c]; }
        else if (row < 512) { if (c >= 768 && c < 1536) v = hidden[(row - 256) * 768 + c - 768]; }
        u16 h, l; bsplit(v, h, l);
        *(u16*)&g_A[0][0][(size_t)row * KP + c] = h;
        *(u16*)&g_A[0][1][(size_t)row * KP + c] = l;
        if (row >= 513 || c >= 1536) {               // set1: pad rows + ext cols zero once
            *(u16*)&g_A[1][0][(size_t)row * KP + c] = 0;
            *(u16*)&g_A[1][1][(size_t)row * KP + c] = 0;
        }
    }
}

// ================= (3) hop0 probs + masked max-pool + ext write, fused =================
// 12 blocks (b,c) x 128 threads; computes p/q for its channel directly from hidden.
__global__ void k_pe0(const float* __restrict__ hidden, const float* __restrict__ cls_w,
                      const float* __restrict__ cls_b, const float* __restrict__ am) {
    int b = blockIdx.x / NC, c = blockIdx.x % NC;
    __shared__ float sw[1536];
    __shared__ float sp[LL], sq[LL], sm[LL];
    int k = threadIdx.x;                             // 128 threads
    for (int e = k; e < 1536; e += LL) sw[e] = cls_w[e * NC + c];
    __syncthreads();
    {
        const float4* hr = (const float4*)(hidden + (size_t)(b * LL + k) * 768);
        const float4* w0 = (const float4*)sw;
        const float4* w1 = (const float4*)(sw + 768);
        float p = 0.f, q = 0.f;
        #pragma unroll 8
        for (int it = 0; it < 192; it++) {
            float4 a = hr[it], x = w0[it], y = w1[it];
            p += a.x * x.x + a.y * x.y + a.z * x.z + a.w * x.w;
            q += a.x * y.x + a.y * y.y + a.z * y.z + a.w * y.w;
        }
        sp[k] = p; sq[k] = q; sm[k] = am[b * LL + k];
    }
    __syncthreads();
    float r  = cls_b[c];                             // hop-0 constant-row probs
    float mk = sm[k], pk = sp[k], qk = sq[k];
    float mx = -INFINITY;
    #pragma unroll 4
    for (int i = 0; i < LL; i++) {
        float mi  = sm[i];
        float mv1 = (i <= k) ? mi * mk : 0.f;
        mx = fmaxf(mx, (sp[i] + qk + r) * mv1);
        float mv2 = (i >= k) ? mk * mi : 0.f;
        mx = fmaxf(mx, (pk + sq[i] + r) * mv2);
    }
    __nv_bfloat16* Ah = g_A[0][0];
    __nv_bfloat16* Al = g_A[0][1];
    int rowP = b * LL + k, rowQ = 256 + b * LL + k;
    u16 h, l;
    bsplit(mx, h, l);
    *(u16*)&Ah[(size_t)rowP * KP + 1536 + c] = h; *(u16*)&Al[(size_t)rowP * KP + 1536 + c] = l;
    *(u16*)&Ah[(size_t)rowQ * KP + 1542 + c] = h; *(u16*)&Al[(size_t)rowQ * KP + 1542 + c] = l;
    bsplit(pk, h, l);
    *(u16*)&Ah[(size_t)rowP * KP + 1548 + c] = h; *(u16*)&Al[(size_t)rowP * KP + 1548 + c] = l;
    bsplit(qk, h, l);
    *(u16*)&Ah[(size_t)rowQ * KP + 1548 + c] = h; *(u16*)&Al[(size_t)rowQ * KP + 1548 + c] = l;
    if (b == 0 && k == 0) {
        bsplit(r, h, l);
        *(u16*)&Ah[(size_t)512 * KP + 1548 + c] = h; *(u16*)&Al[(size_t)512 * KP + 1548 + c] = l;
    }
}

// ================= hop1 pool+ext from pqr2[src] =================
__global__ void k_poolext(const float* __restrict__ am, int src, int set) {
    int b = blockIdx.x / NC, c = blockIdx.x % NC;
    __shared__ float sp[LL], sq[LL], sm[LL];
    const float* pqr = g_pqr2[src];
    __nv_bfloat16* Ah = g_A[set][0];
    __nv_bfloat16* Al = g_A[set][1];
    int k = threadIdx.x;
    sp[k] = pqr[(b * LL + k) * NC + c];
    sq[k] = pqr[(256 + b * LL + k) * NC + c];
    sm[k] = am[b * LL + k];
    __syncthreads();
    float r  = pqr[512 * NC + c];
    float mk = sm[k], pk = sp[k], qk = sq[k];
    float mx = -INFINITY;
    #pragma unroll 4
    for (int i = 0; i < LL; i++) {
        float mi  = sm[i];
        float mv1 = (i <= k) ? mi * mk : 0.f;
        mx = fmaxf(mx, (sp[i] + qk + r) * mv1);
        float mv2 = (i >= k) ? mk * mi : 0.f;
        mx = fmaxf(mx, (pk + sq[i] + r) * mv2);
    }
    int rowP = b * LL + k, rowQ = 256 + b * LL + k;
    u16 h, l;
    bsplit(mx, h, l);
    *(u16*)&Ah[(size_t)rowP * KP + 1536 + c] = h; *(u16*)&Al[(size_t)rowP * KP + 1536 + c] = l;
    *(u16*)&Ah[(size_t)rowQ * KP + 1542 + c] = h; *(u16*)&Al[(size_t)rowQ * KP + 1542 + c] = l;
    bsplit(pk, h, l);
    *(u16*)&Ah[(size_t)rowP * KP + 1548 + c] = h; *(u16*)&Al[(size_t)rowP * KP + 1548 + c] = l;
    bsplit(qk, h, l);
    *(u16*)&Ah[(size_t)rowQ * KP + 1548 + c] = h; *(u16*)&Al[(size_t)rowQ * KP + 1548 + c] = l;
    if (b == 0 && k == 0) {
        bsplit(r, h, l);
        *(u16*)&Ah[(size_t)512 * KP + 1548 + c] = h; *(u16*)&Al[(size_t)512 * KP + 1548 + c] = l;
    }
}

// ================= HMMA split-bf16 GEMM, fused probs epilogue =================
// CTA 128x64, 8 warps (4m x 2n, warp tile 32x32), 3-stage cp.async pipeline.
#define STG 30720     // Ah 10240 | Al 10240 | Bh 5120 | Bl 5120   (pitch 80B)
__global__ void __launch_bounds__(256, 1) k_gemm(int set, const float* __restrict__ bias) {
    extern __shared__ __align__(16) char smem[];
    const __nv_bfloat16* Ah = g_A[set][0];
    const __nv_bfloat16* Al = g_A[set][1];
    __nv_bfloat16* Aoh = g_A[set ^ 1][0];
    __nv_bfloat16* Aol = g_A[set ^ 1][1];

    const int tid = threadIdx.x;
    const int m0 = blockIdx.y * 128, n0 = blockIdx.x * 64;
    const u32 sb = smem_u32(smem);

    const int r4 = tid >> 2, q4 = (tid & 3) * 16;
    const char* gAh = (const char*)Ah + (size_t)(m0 + r4) * (KP * 2) + q4;
    const char* gAl = (const char*)Al + (size_t)(m0 + r4) * (KP * 2) + q4;
    const char* gBh = (const char*)g_Wt[0] + (size_t)(n0 + r4) * (KP * 2) + q4;
    const char* gBl = (const char*)g_Wt[1] + (size_t)(n0 + r4) * (KP * 2) + q4;

    #define COPY_STAGE(s, kt) do {                                            \
        u32 d = sb + (s) * STG;                                               \
        int kb = (kt) * 64;                                                   \
        cpa16(d +         r4 * 80 + q4,        gAh + kb);                     \
        cpa16(d +         (64 + r4) * 80 + q4, gAh + kb + 64 * KP * 2);       \
        cpa16(d + 10240 + r4 * 80 + q4,        gAl + kb);                     \
        cpa16(d + 10240 + (64 + r4) * 80 + q4, gAl + kb + 64 * KP * 2);       \
        cpa16(d + 20480 + r4 * 80 + q4,        gBh + kb);                     \
        cpa16(d + 25600 + r4 * 80 + q4,        gBl + kb);                     \
        asm volatile("cp.async.commit_group;" ::: "memory");                  \
    } while (0)

    COPY_STAGE(0, 0);
    COPY_STAGE(1, 1);

    const int wid = tid >> 5, lane = tid & 31;
    const int wm = wid & 3, wn = wid >> 2;           // warp grid 4(m) x 2(n)
    const int g = lane >> 2, t = lane & 3;
    const u32 a_off = (u32)((wm * 32 + g) * 80 + t * 4);
    const u32 b_off = (u32)(20480 + (wn * 32 + g) * 80 + t * 4);

    float acc[2][4][4];
    #pragma unroll
    for (int mt = 0; mt < 2; mt++)
        #pragma unroll
        for (int nt = 0; nt < 4; nt++)
            #pragma unroll
            for (int i = 0; i < 4; i++) acc[mt][nt][i] = 0.f;

    for (int kt = 0; kt < 50; kt++) {
        if (kt < 49) asm volatile("cp.async.wait_group 1;" ::: "memory");
        else         asm volatile("cp.async.wait_group 0;" ::: "memory");
        __syncthreads();
        u32 st = sb + (kt % 3) * STG;
        #pragma unroll
        for (int kk = 0; kk < 2; kk++) {
            u32 ka = st + a_off + kk * 32;
            u32 kb = st + b_off + kk * 32;
            u32 ah[2][4], al[2][4];
            #pragma unroll
            for (int mt = 0; mt < 2; mt++) {
                u32 base = ka + mt * 1280;
                ah[mt][0] = lds32(base);
                ah[mt][1] = lds32(base + 640);
                ah[mt][2] = lds32(base + 16);
                ah[mt][3] = lds32(base + 656);
                al[mt][0] = lds32(base + 10240);
                al[mt][1] = lds32(base + 10880);
                al[mt][2] = lds32(base + 10256);
                al[mt][3] = lds32(base + 10896);
            }
            #pragma unroll
            for (int nt = 0; nt < 4; nt++) {
                u32 bb  = kb + nt * 640;
                u32 bh0 = lds32(bb),        bh1 = lds32(bb + 16);
                u32 bl0 = lds32(bb + 5120), bl1 = lds32(bb + 5136);
                #pragma unroll
                for (int mt = 0; mt < 2; mt++) {
                    mma16816(acc[mt][nt], ah[mt], bh0, bh1);
                    mma16816(acc[mt][nt], ah[mt], bl0, bl1);
                    mma16816(acc[mt][nt], al[mt], bh0, bh1);
                }
            }
        }
        if (kt + 2 < 50) COPY_STAGE((kt + 2) % 3, kt + 2);
    }

    // ---- epilogue ----
    #pragma unroll
    for (int mt = 0; mt < 2; mt++)
        #pragma unroll
        for (int half = 0; half < 2; half++) {
            int r = m0 + wm * 32 + mt * 16 + g + half * 8;
            if (r == 512) {
                #pragma unroll
                for (int nt = 0; nt < 4; nt++) {
                    int col = n0 + wn * 32 + nt * 8 + t * 2;
                    acc[mt][nt][half * 2]     += bias[col];
                    acc[mt][nt][half * 2 + 1] += bias[col + 1];
                }
            }
        }

    // next-hop bf16 hi/lo A
    #pragma unroll
    for (int mt = 0; mt < 2; mt++)
        #pragma unroll
        for (int nt = 0; nt < 4; nt++) {
            int col = n0 + wn * 32 + nt * 8 + t * 2;
            #pragma unroll
            for (int half = 0; half < 2; half++) {
                int r = m0 + wm * 32 + mt * 16 + g + half * 8;
                if (r < 513) {
                    u16 h0, l0, h1, l1;
                    bsplit(acc[mt][nt][half * 2], h0, l0);
                    bsplit(acc[mt][nt][half * 2 + 1], h1, l1);
                    *(u32*)(Aoh + (size_t)r * KP + col) = (u32)h0 | ((u32)h1 << 16);
                    *(u32*)(Aol + (size_t)r * KP + col) = (u32)l0 | ((u32)l1 << 16);
                }
            }
        }

    // probs partials, transposed layout: g_pp[(r*NC+c)*48 + slab]
    int slab = blockIdx.x * 2 + wn;                  // 0..47
    #pragma unroll
    for (int c = 0; c < NC; c++) {
        float cv[4][2];
        #pragma unroll
        for (int nt = 0; nt < 4; nt++) {
            int col = n0 + wn * 32 + nt * 8 + t * 2;
            cv[nt][0] = g_clsT[c * 1536 + col];
            cv[nt][1] = g_clsT[c * 1536 + col + 1];
        }
        #pragma unroll
        for (int mt = 0; mt < 2; mt++)
            #pragma unroll
            for (int half = 0; half < 2; half++) {
                float s = 0.f;
                #pragma unroll
                for (int nt = 0; nt < 4; nt++)
                    s += acc[mt][nt][half * 2] * cv[nt][0]
                       + acc[mt][nt][half * 2 + 1] * cv[nt][1];
                s += __shfl_xor_sync(0xffffffffu, s, 1);
                s += __shfl_xor_sync(0xffffffffu, s, 2);
                if (t == 0) {
                    int r = m0 + wm * 32 + mt * 16 + g + half * 8;
                    if (r < 513) g_pp[(size_t)(r * NC + c) * 48 + slab] = s;
                }
            }
    }
    #undef COPY_STAGE
}

// ================= reduce probs partials (coalesced contiguous sums) =================
__global__ void k_red(int dst, const float* __restrict__ cls_b) {
    int idx = blockIdx.x * 256 + threadIdx.x;
    if (idx >= 513 * NC) return;
    const float4* pp = (const float4*)(g_pp + (size_t)idx * 48);
    float s = 0.f;
    #pragma unroll
    for (int i = 0; i < 12; i++) {
        float4 v = pp[i];
        s += v.x + v.y + v.z + v.w;
    }
    if (idx >= 512 * NC) s += cls_b[idx - 512 * NC];
    g_pqr2[dst][idx] = s;
}

// ================= final: logits[b,i,j,c] = p + q + r =================
__global__ void k_out(float* __restrict__ out) {
    int idx = blockIdx.x * 256 + threadIdx.x;        // 0..196607 exact
    int c = idx % NC;
    int j = (idx / NC) % LL;
    int t = idx / (NC * LL);
    int i = t % LL;
    int b = t / LL;
    const float* pqr = g_pqr2[0];
    out[idx] = pqr[(b * LL + i) * NC + c]
             + pqr[(256 + b * LL + j) * NC + c]
             + pqr[512 * NC + c];
}

extern "C" void kernel_launch(void* const* d_in, const int* in_sizes, int n_in,
                              void* d_out, int out_size) {
    const float* hidden = (const float*)d_in[0];
    const float* am     = (const float*)d_in[1];
    const float* cls_w  = (const float*)d_in[2];
    const float* cls_b  = (const float*)d_in[3];
    const float* feat_w = (const float*)d_in[4];
    const float* feat_b = (const float*)d_in[5];

    cudaFuncSetAttribute(k_gemm, cudaFuncAttributeMaxDynamicSharedMemorySize, 3 * STG);

    k_convW<<<2400, 256>>>(feat_w, cls_w);           // (1)
    k_init<<<MP, 256>>>(hidden);                     // (2)
    k_pe0<<<12, 128>>>(hidden, cls_w, cls_b, am);    // (3) probs0+pool+ext hop0
    k_gemm<<<dim3(24, 5), 256, 3 * STG>>>(0, feat_b);// (4) <- profiled launch
    k_red<<<13, 256>>>(1, cls_b);                    // (5)
    k_poolext<<<12, 128>>>(am, 1, 1);                // (6)
    k_gemm<<<dim3(24, 5), 256, 3 * STG>>>(1, feat_b);// (7)
    k_red<<<13, 256>>>(0, cls_b);                    // (8)
    k_out<<<768, 256>>>((float*)d_out);              // (9)
}